// round 5
// baseline (speedup 1.0000x reference)
#include <cuda_runtime.h>
#include <cuda_bf16.h>

#define Bsz 512
#define Ssz 512
#define Dsz 64
#define Hsz 128
#define Gsz 512

// ---- LSTM smem layout (bytes) ----
// Wsm: 80 slices x 512 floats = 163840
// hquad: 128 x 16B            = 2048
// partials: 4 b x 3 slots x 128 j x 16B = 24576
#define WSM_OFF  0
#define HQ_OFF   163840
#define PART_OFF (163840 + 2048)
#define LSTM3_SMEM (PART_OFF + 24576)   // 190464

typedef unsigned long long u64;
typedef unsigned int u32;

__device__ float g_pre[(size_t)Bsz * Ssz * Gsz];
__device__ float g_h1[(size_t)Bsz * Ssz * Hsz];
__device__ float g_h2last[Bsz * Hsz];
__device__ float g_whh_t[2 * Hsz * Gsz];
__device__ float g_wih0_t[Dsz * Gsz];
__device__ float g_wih1_t[Hsz * Gsz];
__device__ float g_bias[2 * Gsz];

__device__ __forceinline__ u64 pack2(float x, float y) {
    u64 r; asm("mov.b64 %0, {%1,%2};" : "=l"(r) : "f"(x), "f"(y)); return r;
}
__device__ __forceinline__ void unpack2(u64 v, float &x, float &y) {
    asm("mov.b64 {%0,%1}, %2;" : "=f"(x), "=f"(y) : "l"(v));
}
__device__ __forceinline__ u64 ffma2(u64 a, u64 b, u64 c) {
    u64 d; asm("fma.rn.f32x2 %0, %1, %2, %3;" : "=l"(d) : "l"(a), "l"(b), "l"(c));
    return d;
}
__device__ __forceinline__ u64 addf2(u64 a, u64 b) {
    u64 d; asm("add.rn.f32x2 %0, %1, %2;" : "=l"(d) : "l"(a), "l"(b));
    return d;
}
__device__ __forceinline__ u32 smem_u32(const void* p) {
    u32 a; asm("{ .reg .u64 t; cvta.to.shared.u64 t, %1; cvt.u32.u64 %0, t; }" : "=r"(a) : "l"(p));
    return a;
}
__device__ __forceinline__ void lds_v2(u32 a, u64 &x, u64 &y) {
    asm volatile("ld.shared.v2.u64 {%0,%1}, [%2];" : "=l"(x), "=l"(y) : "r"(a));
}
__device__ __forceinline__ void lds_v4f(u32 a, float &x, float &y, float &z, float &w) {
    asm volatile("ld.shared.v4.f32 {%0,%1,%2,%3}, [%4];" : "=f"(x), "=f"(y), "=f"(z), "=f"(w) : "r"(a));
}
__device__ __forceinline__ u64 lds_64(u32 a) {
    u64 x; asm volatile("ld.shared.u64 %0, [%1];" : "=l"(x) : "r"(a)); return x;
}
__device__ __forceinline__ void sts_v2(u32 a, u64 x, u64 y) {
    asm volatile("st.shared.v2.u64 [%0], {%1,%2};" :: "r"(a), "l"(x), "l"(y));
}
__device__ __forceinline__ void sts_64(u32 a, u64 x) {
    asm volatile("st.shared.u64 [%0], %1;" :: "r"(a), "l"(x));
}
__device__ __forceinline__ void sts_f32(u32 a, float x) {
    asm volatile("st.shared.f32 [%0], %1;" :: "r"(a), "f"(x));
}
__device__ __forceinline__ float tanh_fast(float x) {
    float y; asm("tanh.approx.f32 %0, %1;" : "=f"(y) : "f"(x)); return y;
}
__device__ __forceinline__ float sig_fast(float x) {
    return fmaf(tanh_fast(0.5f * x), 0.5f, 0.5f);
}

// --------------------------------- prep -------------------------------------
__global__ void prep_kernel(const float* __restrict__ Wih0, const float* __restrict__ Whh0,
                            const float* __restrict__ bih0, const float* __restrict__ bhh0,
                            const float* __restrict__ Wih1, const float* __restrict__ Whh1,
                            const float* __restrict__ bih1, const float* __restrict__ bhh1) {
    int tid = blockIdx.x * blockDim.x + threadIdx.x;
    int nt  = gridDim.x * blockDim.x;
    for (int idx = tid; idx < Hsz * Gsz; idx += nt) {
        int k = idx >> 9;
        int jg = idx & 511;
        int j = jg >> 2, g = jg & 3;
        g_whh_t[idx]             = Whh0[(g * Hsz + j) * Hsz + k];
        g_whh_t[Hsz * Gsz + idx] = Whh1[(g * Hsz + j) * Hsz + k];
        {
            int n = idx & 511;
            g_wih1_t[idx] = Wih1[n * Hsz + k];
        }
        if (idx < Dsz * Gsz) {
            int k0 = idx >> 9, n = idx & 511;
            g_wih0_t[idx] = Wih0[n * Dsz + k0];
        }
        if (idx < Gsz) {
            g_bias[idx]       = bih0[idx] + bhh0[idx];
            g_bias[Gsz + idx] = bih1[idx] + bhh1[idx];
        }
    }
}

// ------------------------------ pre GEMM ------------------------------------
template <int K>
__global__ __launch_bounds__(256, 2) void gemm_pre_kernel(
    const float* __restrict__ A, const float* __restrict__ Wt,
    const float* __restrict__ bias, float* __restrict__ C) {
    extern __shared__ float sm[];
    u32 sbase = smem_u32(sm);
    u32 adup = sbase;                 // 128*64 u64
    u32 bsm  = sbase + 65536;         // 64*128 f32
    int tid = threadIdx.x;
    int mb = blockIdx.x, nb = blockIdx.y;

    int tn = tid & 15, tm = tid >> 4;
    int n0 = tn * 8, m0 = tm * 8;

    u64 acc[8][4];
#pragma unroll
    for (int i = 0; i < 8; ++i)
#pragma unroll
        for (int p = 0; p < 4; ++p) acc[i][p] = 0ull;

    const int NCH = K / 64;
#pragma unroll
    for (int ch = 0; ch < NCH; ++ch) {
        if (ch) __syncthreads();
        const float* Ag = A + (size_t)mb * 128 * K + ch * 64;
#pragma unroll
        for (int it = 0; it < 8; ++it) {
            int idx = tid + it * 256;
            int m = idx >> 4, kc = (idx & 15) * 4;
            float4 v = *(const float4*)(Ag + (size_t)m * K + kc);
            u32 dst = adup + (u32)(m * 64 + kc) * 8;
            sts_v2(dst,      pack2(v.x, v.x), pack2(v.y, v.y));
            sts_v2(dst + 16, pack2(v.z, v.z), pack2(v.w, v.w));
        }
#pragma unroll
        for (int it = 0; it < 8; ++it) {
            int idx = tid + it * 256;
            int kr = idx >> 5, n4 = (idx & 31) * 4;
            float4 v = *(const float4*)(Wt + (size_t)(ch * 64 + kr) * Gsz + nb * 128 + n4);
            *(float4*)(sm + 16384 + kr * 128 + n4) = v;
        }
        __syncthreads();

#pragma unroll 2
        for (int k = 0; k < 64; ++k) {
            u64 bp[4];
            lds_v2(bsm + (u32)(k * 128 + n0) * 4,      bp[0], bp[1]);
            lds_v2(bsm + (u32)(k * 128 + n0) * 4 + 16, bp[2], bp[3]);
#pragma unroll
            for (int i = 0; i < 8; ++i) {
                u64 ad = lds_64(adup + (u32)((m0 + i) * 64 + k) * 8);
#pragma unroll
                for (int p = 0; p < 4; ++p) acc[i][p] = ffma2(ad, bp[p], acc[i][p]);
            }
        }
    }

    float4 bs0 = *(const float4*)(bias + nb * 128 + n0);
    float4 bs1 = *(const float4*)(bias + nb * 128 + n0 + 4);
#pragma unroll
    for (int i = 0; i < 8; ++i) {
        float v[8];
        unpack2(acc[i][0], v[0], v[1]); unpack2(acc[i][1], v[2], v[3]);
        unpack2(acc[i][2], v[4], v[5]); unpack2(acc[i][3], v[6], v[7]);
        size_t row = ((size_t)mb * 128 + m0 + i) * Gsz + nb * 128 + n0;
        *(float4*)(C + row)     = make_float4(v[0]+bs0.x, v[1]+bs0.y, v[2]+bs0.z, v[3]+bs0.w);
        *(float4*)(C + row + 4) = make_float4(v[4]+bs1.x, v[5]+bs1.y, v[6]+bs1.z, v[7]+bs1.w);
    }
}

// ------------------------------ LSTM v3 -------------------------------------
// 512 threads: j = tid&127 (hidden unit), grp = tid>>7 (k-quarter + batch owner).
// Batches in f32x2 lanes: acc[gate][pair] where pair0=(b0,b1), pair1=(b2,b3).
// hquad[k] = 16B (h_b0,h_b1,h_b2,h_b3). Group g: k-range [32g,32g+32);
// first 20 k from smem W, last 12 from registers. Epilogue: group g reduces
// and computes activations for batch b0+g only.
template <bool STORE_ALL>
__global__ __launch_bounds__(512) void lstm_kernel(
    const float* __restrict__ pre, const float* __restrict__ whh_t,
    float* __restrict__ hout) {
    extern __shared__ float smf[];
    u32 sb = smem_u32(smf);
    int tid = threadIdx.x;
    int j = tid & 127;
    int g = tid >> 7;
    int b0 = blockIdx.x * 4;

    // stage Wsm: 80 slices; slice s -> k = 32*(s/20) + s%20
    for (int idx = tid * 4; idx < 80 * 512; idx += 2048) {
        int s = idx >> 9, col = idx & 511;
        int k = (s / 20) * 32 + (s % 20);
        *(float4*)(smf + idx) = *(const float4*)(whh_t + (size_t)k * 512 + col);
    }
    // reg W: k = 32g + 20 + r
    float wr[48];
#pragma unroll
    for (int r = 0; r < 12; ++r) {
        float4 w = *(const float4*)(whh_t + (size_t)(32 * g + 20 + r) * 512 + j * 4);
        wr[4*r+0] = w.x; wr[4*r+1] = w.y; wr[4*r+2] = w.z; wr[4*r+3] = w.w;
    }

    u32 hq   = sb + HQ_OFF;
    u32 part = sb + PART_OFF;
    u32 wbase = sb + WSM_OFF + (u32)(20 * g) * 2048 + j * 16;
    u32 hbase = hq + (u32)(32 * g) * 16;

    sts_f32(hq + j * 16 + g * 4, 0.0f);
    float c = 0.0f;
    __syncthreads();

    size_t poff = (size_t)(b0 + g) * Ssz * Gsz;
    float pc[4], pn[4];
#pragma unroll
    for (int e = 0; e < 4; ++e) pc[e] = pre[poff + e * 128 + j];

    for (int t = 0; t < Ssz; ++t) {
        u64 acc[4][2];
#pragma unroll
        for (int e = 0; e < 4; ++e) { acc[e][0] = 0ull; acc[e][1] = 0ull; }

        int tn1 = (t + 1 < Ssz) ? (t + 1) : (Ssz - 1);
#pragma unroll
        for (int e = 0; e < 4; ++e)
            pn[e] = pre[poff + (size_t)tn1 * Gsz + e * 128 + j];

#pragma unroll 4
        for (int ss = 0; ss < 20; ++ss) {
            float wi, wf, wg, wo;
            lds_v4f(wbase + (u32)ss * 2048, wi, wf, wg, wo);
            u64 h01, h23;
            lds_v2(hbase + (u32)ss * 16, h01, h23);
            u64 d;
            d = pack2(wi, wi); acc[0][0] = ffma2(d, h01, acc[0][0]); acc[0][1] = ffma2(d, h23, acc[0][1]);
            d = pack2(wf, wf); acc[1][0] = ffma2(d, h01, acc[1][0]); acc[1][1] = ffma2(d, h23, acc[1][1]);
            d = pack2(wg, wg); acc[2][0] = ffma2(d, h01, acc[2][0]); acc[2][1] = ffma2(d, h23, acc[2][1]);
            d = pack2(wo, wo); acc[3][0] = ffma2(d, h01, acc[3][0]); acc[3][1] = ffma2(d, h23, acc[3][1]);
        }
#pragma unroll 4
        for (int r = 0; r < 12; ++r) {
            u64 h01, h23;
            lds_v2(hbase + (u32)(20 + r) * 16, h01, h23);
            u64 d;
            d = pack2(wr[4*r+0], wr[4*r+0]); acc[0][0] = ffma2(d, h01, acc[0][0]); acc[0][1] = ffma2(d, h23, acc[0][1]);
            d = pack2(wr[4*r+1], wr[4*r+1]); acc[1][0] = ffma2(d, h01, acc[1][0]); acc[1][1] = ffma2(d, h23, acc[1][1]);
            d = pack2(wr[4*r+2], wr[4*r+2]); acc[2][0] = ffma2(d, h01, acc[2][0]); acc[2][1] = ffma2(d, h23, acc[2][1]);
            d = pack2(wr[4*r+3], wr[4*r+3]); acc[3][0] = ffma2(d, h01, acc[3][0]); acc[3][1] = ffma2(d, h23, acc[3][1]);
        }

        // write partials for the 3 batches this group does NOT own
#pragma unroll
        for (int bq = 0; bq < 4; ++bq) {
            if (bq == g) continue;
            int p = bq >> 1, hi = bq & 1;
            float iv0, iv1, fv0, fv1, gv0, gv1, ov0, ov1;
            unpack2(acc[0][p], iv0, iv1);
            unpack2(acc[1][p], fv0, fv1);
            unpack2(acc[2][p], gv0, gv1);
            unpack2(acc[3][p], ov0, ov1);
            float iv = hi ? iv1 : iv0;
            float fv = hi ? fv1 : fv0;
            float gv = hi ? gv1 : gv0;
            float ov = hi ? ov1 : ov0;
            int slot = (g > bq) ? (g - 1) : g;
            u32 pa = part + (u32)((bq * 3 + slot) * 128 + j) * 16;
            sts_v2(pa, pack2(iv, fv), pack2(gv, ov));
        }
        __syncthreads();

        // epilogue for own batch b0+g
        {
            int p = g >> 1, hi = g & 1;
            float iv0, iv1, fv0, fv1, gv0, gv1, ov0, ov1;
            unpack2(acc[0][p], iv0, iv1);
            unpack2(acc[1][p], fv0, fv1);
            unpack2(acc[2][p], gv0, gv1);
            unpack2(acc[3][p], ov0, ov1);
            u64 sif = pack2((hi ? iv1 : iv0) + pc[0], (hi ? fv1 : fv0) + pc[1]);
            u64 sgo = pack2((hi ? gv1 : gv0) + pc[2], (hi ? ov1 : ov0) + pc[3]);
#pragma unroll
            for (int slot = 0; slot < 3; ++slot) {
                u64 qif, qgo;
                lds_v2(part + (u32)((g * 3 + slot) * 128 + j) * 16, qif, qgo);
                sif = addf2(sif, qif);
                sgo = addf2(sgo, qgo);
            }
            float ip, fp, gp, op;
            unpack2(sif, ip, fp);
            unpack2(sgo, gp, op);
            float ig = sig_fast(ip);
            float fg = sig_fast(fp);
            float gg = tanh_fast(gp);
            float og = sig_fast(op);
            c = fg * c + ig * gg;
            float h = og * tanh_fast(c);
            sts_f32(hq + j * 16 + g * 4, h);
            if (STORE_ALL) {
                hout[((size_t)(b0 + g) * Ssz + t) * Hsz + j] = h;
            } else if (t == Ssz - 1) {
                hout[(size_t)(b0 + g) * Hsz + j] = h;
            }
        }
#pragma unroll
        for (int e = 0; e < 4; ++e) pc[e] = pn[e];
        __syncthreads();
    }
}

// ------------------------------- head ---------------------------------------
__global__ void head_kernel(const float* __restrict__ h2, const float* __restrict__ Wlin,
                            const float* __restrict__ blin, float* __restrict__ out) {
    int lane = threadIdx.x & 31;
    int warp = (blockIdx.x * blockDim.x + threadIdx.x) >> 5;
    int nw = (gridDim.x * blockDim.x) >> 5;
    float4 wv = ((const float4*)Wlin)[lane];
    float bl = blin[0];
    for (int b = warp; b < Bsz; b += nw) {
        float4 hv = ((const float4*)(h2 + (size_t)b * Hsz))[lane];
        float s = hv.x * wv.x + hv.y * wv.y + hv.z * wv.z + hv.w * wv.w;
#pragma unroll
        for (int o = 16; o; o >>= 1) s += __shfl_xor_sync(0xFFFFFFFFu, s, o);
        if (lane == 0) out[b] = s + bl;
    }
}

// ------------------------------ launcher ------------------------------------
extern "C" void kernel_launch(void* const* d_in, const int* in_sizes, int n_in,
                              void* d_out, int out_size) {
    const float* x    = (const float*)d_in[0];
    const float* Wih0 = (const float*)d_in[1];
    const float* Whh0 = (const float*)d_in[2];
    const float* bih0 = (const float*)d_in[3];
    const float* bhh0 = (const float*)d_in[4];
    const float* Wih1 = (const float*)d_in[5];
    const float* Whh1 = (const float*)d_in[6];
    const float* bih1 = (const float*)d_in[7];
    const float* bhh1 = (const float*)d_in[8];
    const float* Wlin = (const float*)d_in[9];
    const float* blin = (const float*)d_in[10];
    float* out = (float*)d_out;

    static bool attr_done = false;
    if (!attr_done) {
        cudaFuncSetAttribute(gemm_pre_kernel<Dsz>, cudaFuncAttributeMaxDynamicSharedMemorySize, 98304);
        cudaFuncSetAttribute(gemm_pre_kernel<Hsz>, cudaFuncAttributeMaxDynamicSharedMemorySize, 98304);
        cudaFuncSetAttribute(lstm_kernel<true>,  cudaFuncAttributeMaxDynamicSharedMemorySize, LSTM3_SMEM);
        cudaFuncSetAttribute(lstm_kernel<false>, cudaFuncAttributeMaxDynamicSharedMemorySize, LSTM3_SMEM);
        attr_done = true;
    }

    void *p_pre, *p_h1, *p_h2, *p_whh, *p_w0, *p_w1, *p_bias;
    cudaGetSymbolAddress(&p_pre,  g_pre);
    cudaGetSymbolAddress(&p_h1,   g_h1);
    cudaGetSymbolAddress(&p_h2,   g_h2last);
    cudaGetSymbolAddress(&p_whh,  g_whh_t);
    cudaGetSymbolAddress(&p_w0,   g_wih0_t);
    cudaGetSymbolAddress(&p_w1,   g_wih1_t);
    cudaGetSymbolAddress(&p_bias, g_bias);

    prep_kernel<<<128, 512>>>(Wih0, Whh0, bih0, bhh0, Wih1, Whh1, bih1, bhh1);

    dim3 ggrid(Bsz * Ssz / 128, Gsz / 128);

    gemm_pre_kernel<Dsz><<<ggrid, 256, 98304>>>(
        x, (const float*)p_w0, (const float*)p_bias, (float*)p_pre);

    lstm_kernel<true><<<Bsz / 4, 512, LSTM3_SMEM>>>(
        (const float*)p_pre, (const float*)p_whh, (float*)p_h1);

    gemm_pre_kernel<Hsz><<<ggrid, 256, 98304>>>(
        (const float*)p_h1, (const float*)p_w1,
        (const float*)p_bias + Gsz, (float*)p_pre);

    lstm_kernel<false><<<Bsz / 4, 512, LSTM3_SMEM>>>(
        (const float*)p_pre, (const float*)p_whh + Hsz * Gsz, (float*)p_h2);

    head_kernel<<<8, 256>>>((const float*)p_h2, Wlin, blin, out);
}

// round 6
// speedup vs baseline: 1.2206x; 1.2206x over previous
#include <cuda_runtime.h>
#include <cuda_bf16.h>

#define Bsz 512
#define Ssz 512
#define Dsz 64
#define Hsz 128
#define Gsz 512

// LSTM smem layout (bytes)
#define KSM2 107
#define W_BYTES (KSM2*512*4)            // 219136
#define HD_OFF  W_BYTES                 // hdup2: 4*64*16 = 4096
#define PART_OFF (W_BYTES + 4096)       // partials: 4*128*16 = 8192
#define LSTM2_SMEM (PART_OFF + 8192)    // 231424

typedef unsigned long long u64;
typedef unsigned int u32;

__device__ float g_pre[(size_t)Bsz * Ssz * Gsz];
__device__ float g_h1[(size_t)Bsz * Ssz * Hsz];
__device__ float g_h2last[Bsz * Hsz];
__device__ float g_whh_t[2 * Hsz * Gsz];
__device__ float g_wih0_t[Dsz * Gsz];
__device__ float g_wih1_t[Hsz * Gsz];
__device__ float g_bias[2 * Gsz];

__device__ __forceinline__ u64 pack2(float x, float y) {
    u64 r; asm("mov.b64 %0, {%1,%2};" : "=l"(r) : "f"(x), "f"(y)); return r;
}
__device__ __forceinline__ void unpack2(u64 v, float &x, float &y) {
    asm("mov.b64 {%0,%1}, %2;" : "=f"(x), "=f"(y) : "l"(v));
}
__device__ __forceinline__ u64 ffma2(u64 a, u64 b, u64 c) {
    u64 d; asm("fma.rn.f32x2 %0, %1, %2, %3;" : "=l"(d) : "l"(a), "l"(b), "l"(c));
    return d;
}
__device__ __forceinline__ u64 addf2(u64 a, u64 b) {
    u64 d; asm("add.rn.f32x2 %0, %1, %2;" : "=l"(d) : "l"(a), "l"(b));
    return d;
}
__device__ __forceinline__ u32 smem_u32(const void* p) {
    u32 a; asm("{ .reg .u64 t; cvta.to.shared.u64 t, %1; cvt.u32.u64 %0, t; }" : "=r"(a) : "l"(p));
    return a;
}
__device__ __forceinline__ void lds_v2(u32 a, u64 &x, u64 &y) {
    asm volatile("ld.shared.v2.u64 {%0,%1}, [%2];" : "=l"(x), "=l"(y) : "r"(a));
}
__device__ __forceinline__ u64 lds_64(u32 a) {
    u64 x; asm volatile("ld.shared.u64 %0, [%1];" : "=l"(x) : "r"(a)); return x;
}
__device__ __forceinline__ void sts_v2(u32 a, u64 x, u64 y) {
    asm volatile("st.shared.v2.u64 [%0], {%1,%2};" :: "r"(a), "l"(x), "l"(y));
}
__device__ __forceinline__ void sts_64(u32 a, u64 x) {
    asm volatile("st.shared.u64 [%0], %1;" :: "r"(a), "l"(x));
}
__device__ __forceinline__ float tanh_fast(float x) {
    float y; asm("tanh.approx.f32 %0, %1;" : "=f"(y) : "f"(x)); return y;
}
__device__ __forceinline__ float sig_fast(float x) {
    return fmaf(tanh_fast(0.5f * x), 0.5f, 0.5f);
}

// --------------------------------- prep -------------------------------------
__global__ void prep_kernel(const float* __restrict__ Wih0, const float* __restrict__ Whh0,
                            const float* __restrict__ bih0, const float* __restrict__ bhh0,
                            const float* __restrict__ Wih1, const float* __restrict__ Whh1,
                            const float* __restrict__ bih1, const float* __restrict__ bhh1) {
    int tid = blockIdx.x * blockDim.x + threadIdx.x;
    int nt  = gridDim.x * blockDim.x;
    for (int idx = tid; idx < Hsz * Gsz; idx += nt) {
        int k = idx >> 9;
        int jg = idx & 511;
        int j = jg >> 2, g = jg & 3;
        g_whh_t[idx]             = Whh0[(g * Hsz + j) * Hsz + k];
        g_whh_t[Hsz * Gsz + idx] = Whh1[(g * Hsz + j) * Hsz + k];
        {
            int n = idx & 511;
            g_wih1_t[idx] = Wih1[n * Hsz + k];
        }
        if (idx < Dsz * Gsz) {
            int k0 = idx >> 9, n = idx & 511;
            g_wih0_t[idx] = Wih0[n * Dsz + k0];
        }
        if (idx < Gsz) {
            g_bias[idx]       = bih0[idx] + bhh0[idx];
            g_bias[Gsz + idx] = bih1[idx] + bhh1[idx];
        }
    }
}

// ------------------------------ pre GEMM ------------------------------------
// k-paired inner loop: one lds_v2 fetches A-dup for (k,k+1).
template <int K>
__global__ __launch_bounds__(256, 2) void gemm_pre_kernel(
    const float* __restrict__ A, const float* __restrict__ Wt,
    const float* __restrict__ bias, float* __restrict__ C) {
    extern __shared__ float sm[];
    u32 sbase = smem_u32(sm);
    u32 adup = sbase;                 // 128*64 u64
    u32 bsm  = sbase + 65536;         // 64*128 f32
    int tid = threadIdx.x;
    int mb = blockIdx.x, nb = blockIdx.y;

    int tn = tid & 15, tm = tid >> 4;
    int n0 = tn * 8, m0 = tm * 8;

    u64 acc[8][4];
#pragma unroll
    for (int i = 0; i < 8; ++i)
#pragma unroll
        for (int p = 0; p < 4; ++p) acc[i][p] = 0ull;

    const int NCH = K / 64;
#pragma unroll
    for (int ch = 0; ch < NCH; ++ch) {
        if (ch) __syncthreads();
        const float* Ag = A + (size_t)mb * 128 * K + ch * 64;
#pragma unroll
        for (int it = 0; it < 8; ++it) {
            int idx = tid + it * 256;
            int m = idx >> 4, kc = (idx & 15) * 4;
            float4 v = *(const float4*)(Ag + (size_t)m * K + kc);
            u32 dst = adup + (u32)(m * 64 + kc) * 8;
            sts_v2(dst,      pack2(v.x, v.x), pack2(v.y, v.y));
            sts_v2(dst + 16, pack2(v.z, v.z), pack2(v.w, v.w));
        }
#pragma unroll
        for (int it = 0; it < 8; ++it) {
            int idx = tid + it * 256;
            int kr = idx >> 5, n4 = (idx & 31) * 4;
            float4 v = *(const float4*)(Wt + (size_t)(ch * 64 + kr) * Gsz + nb * 128 + n4);
            *(float4*)(sm + 16384 + kr * 128 + n4) = v;
        }
        __syncthreads();

#pragma unroll 2
        for (int k2 = 0; k2 < 32; ++k2) {
            int k0 = 2 * k2;
            u64 bp0[4], bp1[4];
            lds_v2(bsm + (u32)(k0 * 128 + n0) * 4,            bp0[0], bp0[1]);
            lds_v2(bsm + (u32)(k0 * 128 + n0) * 4 + 16,       bp0[2], bp0[3]);
            lds_v2(bsm + (u32)((k0 + 1) * 128 + n0) * 4,      bp1[0], bp1[1]);
            lds_v2(bsm + (u32)((k0 + 1) * 128 + n0) * 4 + 16, bp1[2], bp1[3]);
#pragma unroll
            for (int i = 0; i < 8; ++i) {
                u64 ad0, ad1;
                lds_v2(adup + (u32)((m0 + i) * 64 + k0) * 8, ad0, ad1);
#pragma unroll
                for (int p = 0; p < 4; ++p) acc[i][p] = ffma2(ad0, bp0[p], acc[i][p]);
#pragma unroll
                for (int p = 0; p < 4; ++p) acc[i][p] = ffma2(ad1, bp1[p], acc[i][p]);
            }
        }
    }

    float4 bs0 = *(const float4*)(bias + nb * 128 + n0);
    float4 bs1 = *(const float4*)(bias + nb * 128 + n0 + 4);
#pragma unroll
    for (int i = 0; i < 8; ++i) {
        float v[8];
        unpack2(acc[i][0], v[0], v[1]); unpack2(acc[i][1], v[2], v[3]);
        unpack2(acc[i][2], v[4], v[5]); unpack2(acc[i][3], v[6], v[7]);
        size_t row = ((size_t)mb * 128 + m0 + i) * Gsz + nb * 128 + n0;
        *(float4*)(C + row)     = make_float4(v[0]+bs0.x, v[1]+bs0.y, v[2]+bs0.z, v[3]+bs0.w);
        *(float4*)(C + row + 4) = make_float4(v[4]+bs1.x, v[5]+bs1.y, v[6]+bs1.z, v[7]+bs1.w);
    }
}

// ------------------------------ LSTM (R4 + balanced epilogue) ---------------
// 256 threads: half0 k 0..63, half1 k 64..127 (107..127 in regs).
// Epilogue split: half h owns batches {2h, 2h+1} — writes partials for the
// other half's batches, reduces + activates its own.
template <bool STORE_ALL>
__global__ __launch_bounds__(256) void lstm_kernel(
    const float* __restrict__ pre, const float* __restrict__ whh_t,
    float* __restrict__ hout) {
    extern __shared__ float smf[];
    u32 sbase = smem_u32(smf);
    int tid = threadIdx.x;
    int j = tid & 127;
    int half = tid >> 7;
    int b0 = blockIdx.x * 4;

    for (int idx = tid * 4; idx < KSM2 * 512; idx += 1024)
        *(float4*)(smf + idx) = *(const float4*)(whh_t + idx);

    u64 wifr[21], wgor[21];
    if (half) {
#pragma unroll
        for (int r = 0; r < 21; ++r) {
            float4 w = *(const float4*)(whh_t + (size_t)(107 + r) * 512 + j * 4);
            wifr[r] = pack2(w.x, w.y);
            wgor[r] = pack2(w.z, w.w);
        }
    }

    u32 hd_base = sbase + HD_OFF;
    u32 part_j  = sbase + PART_OFF + j * 16;
    u32 wrow    = sbase + j * 16;
    u32 hd_slot = hd_base + ((j >> 1) * 16) + ((j & 1) * 8);

    int bown = half * 2;                 // own batches bown, bown+1
    int both = 2 - bown;                 // other half's batches

    float c[2] = {0.f, 0.f};
#pragma unroll
    for (int q = 0; q < 2; ++q)
        sts_64(hd_slot + (bown + q) * 1024, 0ull);
    __syncthreads();

    size_t poff[2];
#pragma unroll
    for (int q = 0; q < 2; ++q) poff[q] = (size_t)(b0 + bown + q) * Ssz * Gsz;

    float pc[2][4], pn[2][4];
#pragma unroll
    for (int q = 0; q < 2; ++q)
#pragma unroll
        for (int g = 0; g < 4; ++g)
            pc[q][g] = pre[poff[q] + j + g * Hsz];

    for (int t = 0; t < Ssz; ++t) {
        u64 aif[4], ago[4];
#pragma unroll
        for (int b = 0; b < 4; ++b) { aif[b] = 0ull; ago[b] = 0ull; }

        int tn1 = (t + 1 < Ssz) ? (t + 1) : (Ssz - 1);
#pragma unroll
        for (int q = 0; q < 2; ++q)
#pragma unroll
            for (int g = 0; g < 4; ++g)
                pn[q][g] = pre[poff[q] + (size_t)tn1 * Gsz + j + g * Hsz];

        if (!half) {
#pragma unroll 4
            for (int i = 0; i < 32; ++i) {          // k = 2i, 2i+1
                u64 w0i, w0g, w1i, w1g;
                lds_v2(wrow + (u32)(2 * i) * 2048,     w0i, w0g);
                lds_v2(wrow + (u32)(2 * i + 1) * 2048, w1i, w1g);
#pragma unroll
                for (int b = 0; b < 4; ++b) {
                    u64 h0, h1;
                    lds_v2(hd_base + (u32)(b * 64 + i) * 16, h0, h1);
                    aif[b] = ffma2(w0i, h0, aif[b]);
                    ago[b] = ffma2(w0g, h0, ago[b]);
                    aif[b] = ffma2(w1i, h1, aif[b]);
                    ago[b] = ffma2(w1g, h1, ago[b]);
                }
            }
        } else {
#pragma unroll 4
            for (int i = 0; i < 21; ++i) {          // k = 64+2i, 65+2i
                int k = 64 + 2 * i;
                u64 w0i, w0g, w1i, w1g;
                lds_v2(wrow + (u32)k * 2048,       w0i, w0g);
                lds_v2(wrow + (u32)(k + 1) * 2048, w1i, w1g);
#pragma unroll
                for (int b = 0; b < 4; ++b) {
                    u64 h0, h1;
                    lds_v2(hd_base + (u32)(b * 64 + 32 + i) * 16, h0, h1);
                    aif[b] = ffma2(w0i, h0, aif[b]);
                    ago[b] = ffma2(w0g, h0, ago[b]);
                    aif[b] = ffma2(w1i, h1, aif[b]);
                    ago[b] = ffma2(w1g, h1, ago[b]);
                }
            }
            {   // k = 106 (smem), pair 53 slot 0
                u64 wi, wg;
                lds_v2(wrow + 106u * 2048, wi, wg);
#pragma unroll
                for (int b = 0; b < 4; ++b) {
                    u64 h = lds_64(hd_base + (u32)(b * 64 + 53) * 16);
                    aif[b] = ffma2(wi, h, aif[b]);
                    ago[b] = ffma2(wg, h, ago[b]);
                }
            }
            {   // k = 107 (reg 0), pair 53 slot 1
#pragma unroll
                for (int b = 0; b < 4; ++b) {
                    u64 h = lds_64(hd_base + (u32)(b * 64 + 53) * 16 + 8);
                    aif[b] = ffma2(wifr[0], h, aif[b]);
                    ago[b] = ffma2(wgor[0], h, ago[b]);
                }
            }
#pragma unroll
            for (int p = 0; p < 10; ++p) {          // k = 108+2p, 109+2p
#pragma unroll
                for (int b = 0; b < 4; ++b) {
                    u64 h0, h1;
                    lds_v2(hd_base + (u32)(b * 64 + 54 + p) * 16, h0, h1);
                    aif[b] = ffma2(wifr[1 + 2 * p], h0, aif[b]);
                    ago[b] = ffma2(wgor[1 + 2 * p], h0, ago[b]);
                    aif[b] = ffma2(wifr[2 + 2 * p], h1, aif[b]);
                    ago[b] = ffma2(wgor[2 + 2 * p], h1, ago[b]);
                }
            }
        }

        // write partials for the OTHER half's batches
#pragma unroll
        for (int q = 0; q < 2; ++q) {
            int b = both + q;
            sts_v2(part_j + b * 2048, aif[b], ago[b]);
        }
        __syncthreads();

        // reduce + activate own batches
#pragma unroll
        for (int q = 0; q < 2; ++q) {
            int b = bown + q;
            u64 pif, pgo;
            lds_v2(part_j + b * 2048, pif, pgo);
            u64 sif = addf2(addf2(aif[b], pif), pack2(pc[q][0], pc[q][1]));
            u64 sgo = addf2(addf2(ago[b], pgo), pack2(pc[q][2], pc[q][3]));
            float ip, fp, gp, op;
            unpack2(sif, ip, fp);
            unpack2(sgo, gp, op);
            float ig = sig_fast(ip);
            float fg = sig_fast(fp);
            float gg = tanh_fast(gp);
            float og = sig_fast(op);
            c[q] = fg * c[q] + ig * gg;
            float h = og * tanh_fast(c[q]);
            sts_64(hd_slot + b * 1024, pack2(h, h));
            if (STORE_ALL) {
                hout[((size_t)(b0 + b) * Ssz + t) * Hsz + j] = h;
            } else if (t == Ssz - 1) {
                hout[(size_t)(b0 + b) * Hsz + j] = h;
            }
        }
#pragma unroll
        for (int q = 0; q < 2; ++q)
#pragma unroll
            for (int g = 0; g < 4; ++g) pc[q][g] = pn[q][g];
        __syncthreads();
    }
}

// ------------------------------- head ---------------------------------------
__global__ void head_kernel(const float* __restrict__ h2, const float* __restrict__ Wlin,
                            const float* __restrict__ blin, float* __restrict__ out) {
    int lane = threadIdx.x & 31;
    int warp = (blockIdx.x * blockDim.x + threadIdx.x) >> 5;
    int nw = (gridDim.x * blockDim.x) >> 5;
    float4 wv = ((const float4*)Wlin)[lane];
    float bl = blin[0];
    for (int b = warp; b < Bsz; b += nw) {
        float4 hv = ((const float4*)(h2 + (size_t)b * Hsz))[lane];
        float s = hv.x * wv.x + hv.y * wv.y + hv.z * wv.z + hv.w * wv.w;
#pragma unroll
        for (int o = 16; o; o >>= 1) s += __shfl_xor_sync(0xFFFFFFFFu, s, o);
        if (lane == 0) out[b] = s + bl;
    }
}

// ------------------------------ launcher ------------------------------------
extern "C" void kernel_launch(void* const* d_in, const int* in_sizes, int n_in,
                              void* d_out, int out_size) {
    const float* x    = (const float*)d_in[0];
    const float* Wih0 = (const float*)d_in[1];
    const float* Whh0 = (const float*)d_in[2];
    const float* bih0 = (const float*)d_in[3];
    const float* bhh0 = (const float*)d_in[4];
    const float* Wih1 = (const float*)d_in[5];
    const float* Whh1 = (const float*)d_in[6];
    const float* bih1 = (const float*)d_in[7];
    const float* bhh1 = (const float*)d_in[8];
    const float* Wlin = (const float*)d_in[9];
    const float* blin = (const float*)d_in[10];
    float* out = (float*)d_out;

    static bool attr_done = false;
    if (!attr_done) {
        cudaFuncSetAttribute(gemm_pre_kernel<Dsz>, cudaFuncAttributeMaxDynamicSharedMemorySize, 98304);
        cudaFuncSetAttribute(gemm_pre_kernel<Hsz>, cudaFuncAttributeMaxDynamicSharedMemorySize, 98304);
        cudaFuncSetAttribute(lstm_kernel<true>,  cudaFuncAttributeMaxDynamicSharedMemorySize, LSTM2_SMEM);
        cudaFuncSetAttribute(lstm_kernel<false>, cudaFuncAttributeMaxDynamicSharedMemorySize, LSTM2_SMEM);
        attr_done = true;
    }

    void *p_pre, *p_h1, *p_h2, *p_whh, *p_w0, *p_w1, *p_bias;
    cudaGetSymbolAddress(&p_pre,  g_pre);
    cudaGetSymbolAddress(&p_h1,   g_h1);
    cudaGetSymbolAddress(&p_h2,   g_h2last);
    cudaGetSymbolAddress(&p_whh,  g_whh_t);
    cudaGetSymbolAddress(&p_w0,   g_wih0_t);
    cudaGetSymbolAddress(&p_w1,   g_wih1_t);
    cudaGetSymbolAddress(&p_bias, g_bias);

    prep_kernel<<<128, 512>>>(Wih0, Whh0, bih0, bhh0, Wih1, Whh1, bih1, bhh1);

    dim3 ggrid(Bsz * Ssz / 128, Gsz / 128);

    gemm_pre_kernel<Dsz><<<ggrid, 256, 98304>>>(
        x, (const float*)p_w0, (const float*)p_bias, (float*)p_pre);

    lstm_kernel<true><<<Bsz / 4, 256, LSTM2_SMEM>>>(
        (const float*)p_pre, (const float*)p_whh, (float*)p_h1);

    gemm_pre_kernel<Hsz><<<ggrid, 256, 98304>>>(
        (const float*)p_h1, (const float*)p_w1,
        (const float*)p_bias + Gsz, (float*)p_pre);

    lstm_kernel<false><<<Bsz / 4, 256, LSTM2_SMEM>>>(
        (const float*)p_pre, (const float*)p_whh + Hsz * Gsz, (float*)p_h2);

    head_kernel<<<8, 256>>>((const float*)p_h2, Wlin, blin, out);
}